// round 5
// baseline (speedup 1.0000x reference)
#include <cuda_runtime.h>

// TrajectoryGenerator fused kernel for GB300 (sm_103a), round 4.
// One warp == 2 scenes (agent pair per lane); fma.rn.f32x2 everywhere;
// rank-2 collapsed input embedding. NEW: hardware tanh.approx for all LSTM
// activations (1 MUFU instead of EX2+RCP chains), unroll-2 cell loop.

#define OBS   20
#define PRED  30
#define WARPS 8
#define TPB   256          // 8 warps, 16 scenes per block

typedef unsigned long long ull;

__device__ __forceinline__ ull ffma2(ull a, ull b, ull c) {
    ull d; asm("fma.rn.f32x2 %0, %1, %2, %3;" : "=l"(d) : "l"(a), "l"(b), "l"(c)); return d;
}
__device__ __forceinline__ ull fadd2_(ull a, ull b) {
    ull d; asm("add.rn.f32x2 %0, %1, %2;" : "=l"(d) : "l"(a), "l"(b)); return d;
}
__device__ __forceinline__ ull dup2(float x) {
    ull d; asm("mov.b64 %0, {%1, %1};" : "=l"(d) : "f"(x)); return d;
}
__device__ __forceinline__ ull pk2(float lo, float hi) {
    ull d; asm("mov.b64 %0, {%1, %2};" : "=l"(d) : "f"(lo), "f"(hi)); return d;
}
__device__ __forceinline__ void unpk(ull a, float& x, float& y) {
    asm("mov.b64 {%0, %1}, %2;" : "=f"(x), "=f"(y) : "l"(a));
}
__device__ __forceinline__ float hsum2(ull a) {
    float x, y; unpk(a, x, y); return x + y;
}
// hardware tanh (MUFU.TANH, 1 op)
__device__ __forceinline__ float tanh_hw(float x) {
    float y; asm("tanh.approx.f32 %0, %1;" : "=f"(y) : "f"(x)); return y;
}
__device__ __forceinline__ float sig_hw(float x) {
    return fmaf(tanh_hw(0.5f * x), 0.5f, 0.5f);
}
__device__ __forceinline__ float leaky(float x)  { return x > 0.f ? x : 0.01f * x; }

template <int NP>
__device__ __forceinline__ float dotp(const ull* a, const float* wrow) {
    const ulonglong2* w = (const ulonglong2*)wrow;
    ull a0 = 0ull, a1 = 0ull;
#pragma unroll
    for (int q = 0; q < NP / 2; q++) {
        ulonglong2 ww = w[q];
        a0 = ffma2(ww.x, a[2 * q], a0);
        a1 = ffma2(ww.y, a[2 * q + 1], a1);
    }
    return hsum2(fadd2_(a0, a1));
}

struct SM {
    float  enc_whh[4096];
    float  dec_whh[4096];
    float  wq[1024], wk[1024], wv[1024], woT[1024];
    float  mlp1[4096];
    float  mlp2[1536];
    float4 gw_enc[128];   // (w2x, w2y, combined_bias, 0) per gate row
    float4 gw_dec[128];
    float  lneg[32], lneb[32], lncg[64], lncb[64];
    float  m1b[64], m2b[24], dow[64], dob[2], noi[8];
    float  stash[WARPS * 4096];   // 16KB/warp: cA | cB | hpA | hpB (1024 f each)
};

struct Params {
    const float* obs_rel;
    const int*   se;
    const float* noise_z;
    const float* eew; const float* eeb;
    const float* e_wih; const float* e_whh; const float* e_bih; const float* e_bhh;
    const float* lneg; const float* lneb;
    const float* wq; const float* wk; const float* wv; const float* wo;
    const float* lncg; const float* lncb;
    const float* m1w; const float* m1b;
    const float* m2w; const float* m2b;
    const float* dew; const float* deb;
    const float* d_wih; const float* d_whh; const float* d_bih; const float* d_bhh;
    const float* dow; const float* dob;
    float* out;
    int n;
    int nscene;
};

__device__ __forceinline__ void cpN(float* dst, const float* src, int n, int tid) {
    for (int i = tid; i < n; i += TPB) dst[i] = src[i];
}

// Double LSTM step: two agents (A,B) per lane sharing one pass over whh.
__device__ __forceinline__ void lstm_step2(const float* whh, const float4* gw,
                                           float xA, float yA, float xB, float yB,
                                           ull* hA, ull* hB,
                                           float* cA, float* cB,
                                           ull* hpA, ull* hpB) {
#pragma unroll 2
    for (int j = 0; j < 16; j++) {
        float hnA[2], hnB[2];
#pragma unroll
        for (int half = 0; half < 2; half++) {
            const int k = 2 * j + half;
            float gA[4], gB[4];
#pragma unroll
            for (int g = 0; g < 4; g++) {
                const int row = g * 32 + k;
                const ulonglong2* w = (const ulonglong2*)(whh + row * 32);
                float4 gv = gw[row];
                ull a0 = 0ull, a1 = 0ull, b0 = 0ull, b1 = 0ull;
#pragma unroll
                for (int q = 0; q < 8; q++) {
                    ulonglong2 ww = w[q];
                    a0 = ffma2(ww.x, hA[2 * q], a0);
                    a1 = ffma2(ww.y, hA[2 * q + 1], a1);
                    b0 = ffma2(ww.x, hB[2 * q], b0);
                    b1 = ffma2(ww.y, hB[2 * q + 1], b1);
                }
                gA[g] = fmaf(gv.x, xA, fmaf(gv.y, yA, gv.z + hsum2(fadd2_(a0, a1))));
                gB[g] = fmaf(gv.x, xB, fmaf(gv.y, yB, gv.z + hsum2(fadd2_(b0, b1))));
            }
            {
                float c = cA[k * 32];
                c = sig_hw(gA[1]) * c + sig_hw(gA[0]) * tanh_hw(gA[2]);
                cA[k * 32] = c;
                hnA[half] = sig_hw(gA[3]) * tanh_hw(c);
            }
            {
                float c = cB[k * 32];
                c = sig_hw(gB[1]) * c + sig_hw(gB[0]) * tanh_hw(gB[2]);
                cB[k * 32] = c;
                hnB[half] = sig_hw(gB[3]) * tanh_hw(c);
            }
        }
        hpA[j * 32] = pk2(hnA[0], hnA[1]);
        hpB[j * 32] = pk2(hnB[0], hnB[1]);
    }
#pragma unroll
    for (int j = 0; j < 16; j++) { hA[j] = hpA[j * 32]; hB[j] = hpB[j * 32]; }
}

// layernorm 32 dims (packed) -> packed output
__device__ __forceinline__ void ln32(const ull* h, const float* gg, const float* bb, ull* o) {
    float m = 0.f;
#pragma unroll
    for (int j = 0; j < 16; j++) m += hsum2(h[j]);
    m *= (1.f / 32.f);
    float var = 0.f;
    float hl[32];
#pragma unroll
    for (int j = 0; j < 16; j++) {
        float a, b; unpk(h[j], a, b);
        a -= m; b -= m;
        var += a * a + b * b;
        hl[2 * j] = a; hl[2 * j + 1] = b;
    }
    var *= (1.f / 32.f);
    float inv = rsqrtf(var + 1e-5f);
#pragma unroll
    for (int j = 0; j < 16; j++)
        o[j] = pk2(hl[2 * j] * inv * gg[2 * j] + bb[2 * j],
                   hl[2 * j + 1] * inv * gg[2 * j + 1] + bb[2 * j + 1]);
}

// per-scene attention + ctx-LN + MLP
__device__ __forceinline__ void attn_mlp(const SM* s, const ull* ln2,
                                         float* kb, float* vb, int lane, ull* dh2) {
    __syncwarp();
#pragma unroll
    for (int i = 0; i < 32; i++)
        kb[lane * 32 + (i ^ lane)] = dotp<16>(ln2, s->wk + i * 32);
#pragma unroll
    for (int i = 0; i < 32; i++)
        vb[lane * 32 + (i ^ lane)] = dotp<16>(ln2, s->wv + i * 32);
    __syncwarp();

    ull o2[16];
#pragma unroll
    for (int q = 0; q < 16; q++) o2[q] = 0ull;

#pragma unroll 1
    for (int hh = 0; hh < 4; hh++) {
        float qh[8];
#pragma unroll
        for (int i = 0; i < 8; i++) qh[i] = dotp<16>(ln2, s->wq + (hh * 8 + i) * 32);
        float sc[32];
        float mx = -3.4e38f;
#pragma unroll
        for (int key = 0; key < 32; key++) {
            float d = 0.f;
#pragma unroll
            for (int i = 0; i < 8; i++)
                d += qh[i] * kb[key * 32 + ((hh * 8 + i) ^ key)];
            d *= 0.3535533905932738f;
            sc[key] = d;
            mx = fmaxf(mx, d);
        }
        float ssum = 0.f;
#pragma unroll
        for (int key = 0; key < 32; key++) {
            float e = __expf(sc[key] - mx);
            sc[key] = e; ssum += e;
        }
        float sinv = __fdividef(1.f, ssum);
        float av[8];
#pragma unroll
        for (int i = 0; i < 8; i++) av[i] = 0.f;
#pragma unroll
        for (int key = 0; key < 32; key++) {
            float pw = sc[key];
#pragma unroll
            for (int i = 0; i < 8; i++)
                av[i] += pw * vb[key * 32 + ((hh * 8 + i) ^ key)];
        }
#pragma unroll
        for (int i = 0; i < 8; i++) {
            ull ad = dup2(av[i] * sinv);
            const ulonglong2* wt = (const ulonglong2*)(s->woT + (hh * 8 + i) * 32);
#pragma unroll
            for (int q = 0; q < 8; q++) {
                ulonglong2 w = wt[q];
                o2[2 * q]     = ffma2(w.x, ad, o2[2 * q]);
                o2[2 * q + 1] = ffma2(w.y, ad, o2[2 * q + 1]);
            }
        }
    }

    // ctx layernorm over concat(ln2, o2) (64 dims)
    float m2 = 0.f;
#pragma unroll
    for (int j = 0; j < 16; j++) m2 += hsum2(ln2[j]) + hsum2(o2[j]);
    m2 *= (1.f / 64.f);
    float cv[64];
    float v2 = 0.f;
#pragma unroll
    for (int j = 0; j < 16; j++) {
        float a, b; unpk(ln2[j], a, b);
        a -= m2; b -= m2; v2 += a * a + b * b;
        cv[2 * j] = a; cv[2 * j + 1] = b;
    }
#pragma unroll
    for (int j = 0; j < 16; j++) {
        float a, b; unpk(o2[j], a, b);
        a -= m2; b -= m2; v2 += a * a + b * b;
        cv[32 + 2 * j] = a; cv[33 + 2 * j] = b;
    }
    v2 *= (1.f / 64.f);
    float inv2 = rsqrtf(v2 + 1e-5f);
    ull ctx2[32];
#pragma unroll
    for (int q = 0; q < 32; q++)
        ctx2[q] = pk2(cv[2 * q] * inv2 * s->lncg[2 * q] + s->lncb[2 * q],
                      cv[2 * q + 1] * inv2 * s->lncg[2 * q + 1] + s->lncb[2 * q + 1]);

    ull x12[32];
#pragma unroll
    for (int q = 0; q < 32; q++) {
        float y0 = leaky(dotp<32>(ctx2, s->mlp1 + (2 * q) * 64) + s->m1b[2 * q]);
        float y1 = leaky(dotp<32>(ctx2, s->mlp1 + (2 * q + 1) * 64) + s->m1b[2 * q + 1]);
        x12[q] = pk2(y0, y1);
    }
#pragma unroll
    for (int q = 0; q < 12; q++) {
        float y0 = leaky(dotp<32>(x12, s->mlp2 + (2 * q) * 64) + s->m2b[2 * q]);
        float y1 = leaky(dotp<32>(x12, s->mlp2 + (2 * q + 1) * 64) + s->m2b[2 * q + 1]);
        dh2[q] = pk2(y0, y1);
    }
#pragma unroll
    for (int q = 0; q < 4; q++)
        dh2[12 + q] = pk2(s->noi[2 * q], s->noi[2 * q + 1]);
}

__global__ void __launch_bounds__(TPB)
traj_kernel(Params p) {
    extern __shared__ float smem_raw[];
    SM* s = (SM*)smem_raw;
    const int tid = threadIdx.x, warp = tid >> 5, lane = tid & 31;

    // ---- stage weights ----
    cpN(s->enc_whh, p.e_whh, 4096, tid);
    cpN(s->dec_whh, p.d_whh, 4096, tid);
    cpN(s->wq, p.wq, 1024, tid);
    cpN(s->wk, p.wk, 1024, tid);
    cpN(s->wv, p.wv, 1024, tid);
    for (int i = tid; i < 1024; i += TPB) {
        int r = i >> 5, c = i & 31;
        s->woT[i] = p.wo[c * 32 + r];
    }
    cpN(s->mlp1, p.m1w, 4096, tid);
    cpN(s->mlp2, p.m2w, 1536, tid);
    // rank-2 collapsed input weights + combined bias (one row per thread)
    {
        int row = tid & 127;
        const float* wih   = (tid < 128) ? p.e_wih : p.d_wih;
        const float* emw   = (tid < 128) ? p.eew   : p.dew;
        const float* emb_b = (tid < 128) ? p.eeb   : p.deb;
        const float* bih   = (tid < 128) ? p.e_bih : p.d_bih;
        const float* bhh   = (tid < 128) ? p.e_bhh : p.d_bhh;
        float wx = 0.f, wy = 0.f, cb = 0.f;
#pragma unroll
        for (int j = 0; j < 16; j++) {
            float w = wih[row * 16 + j];
            wx += w * emw[j * 2 + 0];
            wy += w * emw[j * 2 + 1];
            cb += w * emb_b[j];
        }
        cb += bih[row] + bhh[row];
        float4 v = make_float4(wx, wy, cb, 0.f);
        if (tid < 128) s->gw_enc[row] = v; else s->gw_dec[row] = v;
    }
    cpN(s->lneg, p.lneg, 32, tid);
    cpN(s->lneb, p.lneb, 32, tid);
    cpN(s->lncg, p.lncg, 64, tid);
    cpN(s->lncb, p.lncb, 64, tid);
    cpN(s->m1b, p.m1b, 64, tid);
    cpN(s->m2b, p.m2b, 24, tid);
    cpN(s->dow, p.dow, 64, tid);
    cpN(s->dob, p.dob, 2, tid);
    cpN(s->noi, p.noise_z, 8, tid);
    __syncthreads();

    const int sceneA = (blockIdx.x * WARPS + warp) * 2;
    if (sceneA >= p.nscene) return;
    const int sceneB = sceneA + 1;
    const bool hasB = (sceneB < p.nscene);
    const int baseA = p.se[2 * sceneA];
    const int baseB = hasB ? p.se[2 * sceneB] : baseA;
    const int agA = baseA + lane;
    const int agB = baseB + lane;

    float* wst = s->stash + warp * 4096;
    float* cA = wst + lane;                       // [k*32]
    float* cB = wst + 1024 + lane;
    ull*  hpA = (ull*)(wst + 2048) + lane;        // [j*32]
    ull*  hpB = (ull*)(wst + 3072) + lane;

    // ---- encoder ----
#pragma unroll
    for (int k = 0; k < 32; k++) { cA[k * 32] = 0.f; cB[k * 32] = 0.f; }
    ull hA[16], hB[16];
#pragma unroll
    for (int j = 0; j < 16; j++) { hA[j] = 0ull; hB[j] = 0ull; }

    float lxA = 0.f, lyA = 0.f, lxB = 0.f, lyB = 0.f;
#pragma unroll 1
    for (int t = 0; t < OBS; t++) {
        float2 a = *(const float2*)(p.obs_rel + ((size_t)t * p.n + agA) * 2);
        float2 b = *(const float2*)(p.obs_rel + ((size_t)t * p.n + agB) * 2);
        lstm_step2(s->enc_whh, s->gw_enc, a.x, a.y, b.x, b.y, hA, hB, cA, cB, hpA, hpB);
        lxA = a.x; lyA = a.y; lxB = b.x; lyB = b.y;
    }

    // ---- LN of both agents ----
    ull lnA[16], lnB[16];
    ln32(hA, s->lneg, s->lneb, lnA);
    ln32(hB, s->lneg, s->lneb, lnB);

    // ---- attention + MLP, scene A then scene B (kb/vb reuse c region) ----
    float* kb = wst;          // c state dead until decoder re-init
    float* vb = wst + 1024;
    ull dhA[16], dhB[16];
    attn_mlp(s, lnA, kb, vb, lane, dhA);
    // park dhA in hp region while doing scene B
#pragma unroll
    for (int j = 0; j < 16; j++) hpA[j * 32] = dhA[j];
    attn_mlp(s, lnB, kb, vb, lane, dhB);
#pragma unroll
    for (int j = 0; j < 16; j++) dhA[j] = hpA[j * 32];

    // ---- decoder ----
    __syncwarp();
#pragma unroll
    for (int k = 0; k < 32; k++) { cA[k * 32] = 0.f; cB[k * 32] = 0.f; }

    float rxA = lxA, ryA = lyA, rxB = lxB, ryB = lyB;
#pragma unroll 1
    for (int t = 0; t < PRED; t++) {
        lstm_step2(s->dec_whh, s->gw_dec, rxA, ryA, rxB, ryB, dhA, dhB, cA, cB, hpA, hpB);
        float a0 = dotp<16>(dhA, s->dow) + s->dob[0];
        float a1 = dotp<16>(dhA, s->dow + 32) + s->dob[1];
        float b0 = dotp<16>(dhB, s->dow) + s->dob[0];
        float b1 = dotp<16>(dhB, s->dow + 32) + s->dob[1];
        *(float2*)(p.out + ((size_t)t * p.n + agA) * 2) = make_float2(a0, a1);
        if (hasB)
            *(float2*)(p.out + ((size_t)t * p.n + agB) * 2) = make_float2(b0, b1);
        rxA = a0; ryA = a1; rxB = b0; ryB = b1;
    }
}

extern "C" void kernel_launch(void* const* d_in, const int* in_sizes, int n_in,
                              void* d_out, int out_size) {
    Params p;
    p.obs_rel = (const float*)d_in[1];
    p.se      = (const int*)d_in[2];
    p.noise_z = (const float*)d_in[3];
    p.eew = (const float*)d_in[4];   p.eeb = (const float*)d_in[5];
    p.e_wih = (const float*)d_in[6]; p.e_whh = (const float*)d_in[7];
    p.e_bih = (const float*)d_in[8]; p.e_bhh = (const float*)d_in[9];
    p.lneg = (const float*)d_in[10]; p.lneb = (const float*)d_in[11];
    p.wq = (const float*)d_in[12];   p.wk = (const float*)d_in[13];
    p.wv = (const float*)d_in[14];   p.wo = (const float*)d_in[15];
    p.lncg = (const float*)d_in[16]; p.lncb = (const float*)d_in[17];
    p.m1w = (const float*)d_in[18];  p.m1b = (const float*)d_in[19];
    p.m2w = (const float*)d_in[20];  p.m2b = (const float*)d_in[21];
    p.dew = (const float*)d_in[22];  p.deb = (const float*)d_in[23];
    p.d_wih = (const float*)d_in[24]; p.d_whh = (const float*)d_in[25];
    p.d_bih = (const float*)d_in[26]; p.d_bhh = (const float*)d_in[27];
    p.dow = (const float*)d_in[28];  p.dob = (const float*)d_in[29];
    p.out = (float*)d_out;
    p.n = in_sizes[1] / (OBS * 2);
    p.nscene = in_sizes[2] / 2;

    size_t smem = sizeof(SM);
    cudaFuncSetAttribute(traj_kernel, cudaFuncAttributeMaxDynamicSharedMemorySize, (int)smem);
    int scenesPerBlock = 2 * WARPS;
    int grid = (p.nscene + scenesPerBlock - 1) / scenesPerBlock;
    traj_kernel<<<grid, TPB, smem>>>(p);
}

// round 10
// speedup vs baseline: 1.1866x; 1.1866x over previous
#include <cuda_runtime.h>

// TrajectoryGenerator, round 5: 3-kernel split (enc LSTM / attn+MLP / dec LSTM)
// via __device__ scratch. LSTM kernels: 448 thr (14 warps), 28 scenes/CTA,
// grid=147 (one full wave), 2 agents per lane, rank-2 collapsed input with
// bias/xy folded into packed accumulator inits. fma.rn.f32x2 + tanh.approx.

#define OBS   20
#define PRED  30
#define MAXN  131072

typedef unsigned long long ull;

__device__ static float g_henc[MAXN * 32];   // raw encoder h
__device__ static float g_dh[MAXN * 32];     // decoder initial h

__device__ __forceinline__ ull ffma2(ull a, ull b, ull c) {
    ull d; asm("fma.rn.f32x2 %0, %1, %2, %3;" : "=l"(d) : "l"(a), "l"(b), "l"(c)); return d;
}
__device__ __forceinline__ ull fmul2(ull a, ull b) {
    ull d; asm("mul.rn.f32x2 %0, %1, %2;" : "=l"(d) : "l"(a), "l"(b)); return d;
}
__device__ __forceinline__ ull fadd2_(ull a, ull b) {
    ull d; asm("add.rn.f32x2 %0, %1, %2;" : "=l"(d) : "l"(a), "l"(b)); return d;
}
__device__ __forceinline__ ull dup2(float x) {
    ull d; asm("mov.b64 %0, {%1, %1};" : "=l"(d) : "f"(x)); return d;
}
__device__ __forceinline__ ull pk2(float lo, float hi) {
    ull d; asm("mov.b64 %0, {%1, %2};" : "=l"(d) : "f"(lo), "f"(hi)); return d;
}
__device__ __forceinline__ void unpk(ull a, float& x, float& y) {
    asm("mov.b64 {%0, %1}, %2;" : "=f"(x), "=f"(y) : "l"(a));
}
__device__ __forceinline__ float hsum2(ull a) {
    float x, y; unpk(a, x, y); return x + y;
}
__device__ __forceinline__ float tanh_hw(float x) {
    float y; asm("tanh.approx.f32 %0, %1;" : "=f"(y) : "f"(x)); return y;
}
__device__ __forceinline__ float leaky(float x) { return x > 0.f ? x : 0.01f * x; }

template <int NP>
__device__ __forceinline__ float dotp(const ull* a, const float* wrow) {
    const ulonglong2* w = (const ulonglong2*)wrow;
    ull a0 = 0ull, a1 = 0ull;
#pragma unroll
    for (int q = 0; q < NP / 2; q++) {
        ulonglong2 ww = w[q];
        a0 = ffma2(ww.x, a[2 * q], a0);
        a1 = ffma2(ww.y, a[2 * q + 1], a1);
    }
    return hsum2(fadd2_(a0, a1));
}

// ============================ LSTM kernels ============================
// Per-warp stash: cA(1024f) | cB(1024f) | hpA(1024f as 512 ull)
#define LWARPS 14
#define LTPB   448
#define SCN_BLK 28

struct LP {
    const float* whh;      // [128,32]
    const float* wih;      // [128,16]
    const float* emw;      // [16,2]
    const float* emb;      // [16]
    const float* bih; const float* bhh;
    const float* obs_rel;  // enc: input; dec: last-frame source
    const int*   se;
    const float* dow; const float* dob;   // dec only
    float* out;                            // dec only
    int n; int nscene;
};

struct SML {
    float      whh[4096];
    ulonglong2 gw[128];     // .x = (wx,wy) packed, .y = (bias, 0)
    float      dow[64];
    float      dob[2];
    float      stash[LWARPS * 3072];
};

// One step for two agents. Old h in hA/hB regs; new A h staged via smem hpA,
// new B h staged in registers. c states in smem.
__device__ __forceinline__ void lstm_step2(const float* whh, const ulonglong2* gw,
                                           ull xyA, ull xyB,
                                           ull* hA, ull* hB,
                                           float* cA, float* cB, ull* hpA) {
    ull hBn[16];
#pragma unroll 1
    for (int j = 0; j < 16; j++) {
        float hnA[2], hnB[2];
#pragma unroll
        for (int half = 0; half < 2; half++) {
            const int k = 2 * j + half;
            float gA[4], gB[4];
#pragma unroll
            for (int g = 0; g < 4; g++) {
                const int row = g * 32 + k;
                const ulonglong2* w = (const ulonglong2*)(whh + row * 32);
                ulonglong2 gv = gw[row];
                ull a0 = gv.y, b0 = gv.y;           // (bias, 0)
                ull a1 = fmul2(gv.x, xyA);
                ull b1 = fmul2(gv.x, xyB);
#pragma unroll
                for (int q = 0; q < 8; q++) {
                    ulonglong2 ww = w[q];
                    a0 = ffma2(ww.x, hA[2 * q], a0);
                    a1 = ffma2(ww.y, hA[2 * q + 1], a1);
                    b0 = ffma2(ww.x, hB[2 * q], b0);
                    b1 = ffma2(ww.y, hB[2 * q + 1], b1);
                }
                gA[g] = hsum2(fadd2_(a0, a1));
                gB[g] = hsum2(fadd2_(b0, b1));
            }
            {
                float tf = tanh_hw(0.5f * gA[1]);
                float ti = tanh_hw(0.5f * gA[0]);
                float tg = tanh_hw(gA[2]);
                float to = tanh_hw(0.5f * gA[3]);
                float c = cA[k * 32];
                float hc = 0.5f * c, hg = 0.5f * tg;
                c = fmaf(tf, hc, hc) + fmaf(ti, hg, hg);
                cA[k * 32] = c;
                float tc = tanh_hw(c);
                float htc = 0.5f * tc;
                hnA[half] = fmaf(to, htc, htc);
            }
            {
                float tf = tanh_hw(0.5f * gB[1]);
                float ti = tanh_hw(0.5f * gB[0]);
                float tg = tanh_hw(gB[2]);
                float to = tanh_hw(0.5f * gB[3]);
                float c = cB[k * 32];
                float hc = 0.5f * c, hg = 0.5f * tg;
                c = fmaf(tf, hc, hc) + fmaf(ti, hg, hg);
                cB[k * 32] = c;
                float tc = tanh_hw(c);
                float htc = 0.5f * tc;
                hnB[half] = fmaf(to, htc, htc);
            }
        }
        hpA[j * 32] = pk2(hnA[0], hnA[1]);
        hBn[j] = pk2(hnB[0], hnB[1]);
    }
#pragma unroll
    for (int j = 0; j < 16; j++) { hA[j] = hpA[j * 32]; hB[j] = hBn[j]; }
}

// staging of collapsed input weights: one row per thread (tid<128)
__device__ __forceinline__ void stage_lstm_smem(SML* s, const LP& p, int tid, int tpb, bool dec) {
    for (int i = tid; i < 4096; i += tpb) s->whh[i] = p.whh[i];
    if (tid < 128) {
        int row = tid;
        float wx = 0.f, wy = 0.f, cb = 0.f;
#pragma unroll
        for (int j = 0; j < 16; j++) {
            float w = p.wih[row * 16 + j];
            wx += w * p.emw[j * 2 + 0];
            wy += w * p.emw[j * 2 + 1];
            cb += w * p.emb[j];
        }
        cb += p.bih[row] + p.bhh[row];
        ulonglong2 v;
        v.x = pk2(wx, wy);
        v.y = pk2(cb, 0.f);
        s->gw[row] = v;
    }
    if (dec) {
        for (int i = tid; i < 64; i += tpb) s->dow[i] = p.dow[i];
        if (tid < 2) s->dob[tid] = p.dob[tid];
    }
}

__global__ void __launch_bounds__(LTPB, 1)
enc_kernel(LP p) {
    extern __shared__ float smraw[];
    SML* s = (SML*)smraw;
    const int tid = threadIdx.x, warp = tid >> 5, lane = tid & 31;
    stage_lstm_smem(s, p, tid, LTPB, false);
    __syncthreads();

    const int sceneA = blockIdx.x * SCN_BLK + warp * 2;
    if (sceneA >= p.nscene) return;
    const bool hasB = (sceneA + 1 < p.nscene);
    const int agA = p.se[2 * sceneA] + lane;
    const int agB = (hasB ? p.se[2 * (sceneA + 1)] : p.se[2 * sceneA]) + lane;

    float* wst = s->stash + warp * 3072;
    float* cA = wst + lane;
    float* cB = wst + 1024 + lane;
    ull*  hpA = (ull*)(wst + 2048) + lane;

#pragma unroll
    for (int k = 0; k < 32; k++) { cA[k * 32] = 0.f; cB[k * 32] = 0.f; }
    ull hA[16], hB[16];
#pragma unroll
    for (int j = 0; j < 16; j++) { hA[j] = 0ull; hB[j] = 0ull; }

#pragma unroll 1
    for (int t = 0; t < OBS; t++) {
        float2 a = *(const float2*)(p.obs_rel + ((size_t)t * p.n + agA) * 2);
        float2 b = *(const float2*)(p.obs_rel + ((size_t)t * p.n + agB) * 2);
        lstm_step2(s->whh, s->gw, pk2(a.x, a.y), pk2(b.x, b.y), hA, hB, cA, cB, hpA);
    }

    ulonglong2* oA = (ulonglong2*)(g_henc + (size_t)agA * 32);
    ulonglong2* oB = (ulonglong2*)(g_henc + (size_t)agB * 32);
#pragma unroll
    for (int q = 0; q < 8; q++) {
        ulonglong2 va; va.x = hA[2 * q]; va.y = hA[2 * q + 1];
        oA[q] = va;
        if (hasB) { ulonglong2 vb; vb.x = hB[2 * q]; vb.y = hB[2 * q + 1]; oB[q] = vb; }
    }
}

__global__ void __launch_bounds__(LTPB, 1)
dec_kernel(LP p) {
    extern __shared__ float smraw[];
    SML* s = (SML*)smraw;
    const int tid = threadIdx.x, warp = tid >> 5, lane = tid & 31;
    stage_lstm_smem(s, p, tid, LTPB, true);
    __syncthreads();

    const int sceneA = blockIdx.x * SCN_BLK + warp * 2;
    if (sceneA >= p.nscene) return;
    const bool hasB = (sceneA + 1 < p.nscene);
    const int agA = p.se[2 * sceneA] + lane;
    const int agB = (hasB ? p.se[2 * (sceneA + 1)] : p.se[2 * sceneA]) + lane;

    float* wst = s->stash + warp * 3072;
    float* cA = wst + lane;
    float* cB = wst + 1024 + lane;
    ull*  hpA = (ull*)(wst + 2048) + lane;

#pragma unroll
    for (int k = 0; k < 32; k++) { cA[k * 32] = 0.f; cB[k * 32] = 0.f; }

    ull hA[16], hB[16];
    {
        const ulonglong2* iA = (const ulonglong2*)(g_dh + (size_t)agA * 32);
        const ulonglong2* iB = (const ulonglong2*)(g_dh + (size_t)agB * 32);
#pragma unroll
        for (int q = 0; q < 8; q++) {
            ulonglong2 va = iA[q]; hA[2 * q] = va.x; hA[2 * q + 1] = va.y;
            ulonglong2 vb = iB[q]; hB[2 * q] = vb.x; hB[2 * q + 1] = vb.y;
        }
    }

    float2 a0v = *(const float2*)(p.obs_rel + ((size_t)(OBS - 1) * p.n + agA) * 2);
    float2 b0v = *(const float2*)(p.obs_rel + ((size_t)(OBS - 1) * p.n + agB) * 2);
    ull xyA = pk2(a0v.x, a0v.y), xyB = pk2(b0v.x, b0v.y);

#pragma unroll 1
    for (int t = 0; t < PRED; t++) {
        lstm_step2(s->whh, s->gw, xyA, xyB, hA, hB, cA, cB, hpA);
        float a0 = dotp<16>(hA, s->dow) + s->dob[0];
        float a1 = dotp<16>(hA, s->dow + 32) + s->dob[1];
        float b0 = dotp<16>(hB, s->dow) + s->dob[0];
        float b1 = dotp<16>(hB, s->dow + 32) + s->dob[1];
        *(float2*)(p.out + ((size_t)t * p.n + agA) * 2) = make_float2(a0, a1);
        if (hasB)
            *(float2*)(p.out + ((size_t)t * p.n + agB) * 2) = make_float2(b0, b1);
        xyA = pk2(a0, a1); xyB = pk2(b0, b1);
    }
}

// ============================ attention kernel ============================
#define AWARPS 8
#define ATPB   256

struct AP {
    const int*   se;
    const float* noise_z;
    const float* lneg; const float* lneb;
    const float* wq; const float* wk; const float* wv; const float* wo;
    const float* lncg; const float* lncb;
    const float* m1w; const float* m1b;
    const float* m2w; const float* m2b;
    int n; int nscene;
};

struct SMA {
    float wq[1024], wk[1024], wv[1024], woT[1024];
    float mlp1[4096];
    float mlp2[1536];
    float lneg[32], lneb[32], lncg[64], lncb[64];
    float m1b[64], m2b[24], noi[8];
    float kv[AWARPS * 2048];
};

__global__ void __launch_bounds__(ATPB)
attn_kernel(AP p) {
    extern __shared__ float smraw[];
    SMA* s = (SMA*)smraw;
    const int tid = threadIdx.x, warp = tid >> 5, lane = tid & 31;

    for (int i = tid; i < 1024; i += ATPB) { s->wq[i] = p.wq[i]; s->wk[i] = p.wk[i]; s->wv[i] = p.wv[i]; }
    for (int i = tid; i < 1024; i += ATPB) { int r = i >> 5, c = i & 31; s->woT[i] = p.wo[c * 32 + r]; }
    for (int i = tid; i < 4096; i += ATPB) s->mlp1[i] = p.m1w[i];
    for (int i = tid; i < 1536; i += ATPB) s->mlp2[i] = p.m2w[i];
    for (int i = tid; i < 32; i += ATPB) { s->lneg[i] = p.lneg[i]; s->lneb[i] = p.lneb[i]; }
    for (int i = tid; i < 64; i += ATPB) { s->lncg[i] = p.lncg[i]; s->lncb[i] = p.lncb[i]; s->m1b[i] = p.m1b[i]; }
    for (int i = tid; i < 24; i += ATPB) s->m2b[i] = p.m2b[i];
    for (int i = tid; i < 8; i += ATPB) s->noi[i] = p.noise_z[i];
    __syncthreads();

    const int scene = blockIdx.x * AWARPS + warp;
    if (scene >= p.nscene) return;
    const int ag = p.se[2 * scene] + lane;

    // load h_enc and layernorm
    ull h[16];
    {
        const ulonglong2* ip = (const ulonglong2*)(g_henc + (size_t)ag * 32);
#pragma unroll
        for (int q = 0; q < 8; q++) { ulonglong2 v = ip[q]; h[2 * q] = v.x; h[2 * q + 1] = v.y; }
    }
    float m = 0.f;
#pragma unroll
    for (int j = 0; j < 16; j++) m += hsum2(h[j]);
    m *= (1.f / 32.f);
    float var = 0.f;
    float hl[32];
#pragma unroll
    for (int j = 0; j < 16; j++) {
        float a, b; unpk(h[j], a, b);
        a -= m; b -= m; var += a * a + b * b;
        hl[2 * j] = a; hl[2 * j + 1] = b;
    }
    var *= (1.f / 32.f);
    float inv = rsqrtf(var + 1e-5f);
    ull ln2[16];
#pragma unroll
    for (int j = 0; j < 16; j++)
        ln2[j] = pk2(hl[2 * j] * inv * s->lneg[2 * j] + s->lneb[2 * j],
                     hl[2 * j + 1] * inv * s->lneg[2 * j + 1] + s->lneb[2 * j + 1]);

    float* kb = s->kv + warp * 2048;
    float* vb = kb + 1024;
#pragma unroll
    for (int i = 0; i < 32; i++)
        kb[lane * 32 + (i ^ lane)] = dotp<16>(ln2, s->wk + i * 32);
#pragma unroll
    for (int i = 0; i < 32; i++)
        vb[lane * 32 + (i ^ lane)] = dotp<16>(ln2, s->wv + i * 32);
    __syncwarp();

    ull o2[16];
#pragma unroll
    for (int q = 0; q < 16; q++) o2[q] = 0ull;

#pragma unroll 1
    for (int hh = 0; hh < 4; hh++) {
        float qh[8];
#pragma unroll
        for (int i = 0; i < 8; i++) qh[i] = dotp<16>(ln2, s->wq + (hh * 8 + i) * 32);
        float sc[32];
        float mx = -3.4e38f;
#pragma unroll
        for (int key = 0; key < 32; key++) {
            float d = 0.f;
#pragma unroll
            for (int i = 0; i < 8; i++)
                d += qh[i] * kb[key * 32 + ((hh * 8 + i) ^ key)];
            d *= 0.3535533905932738f;
            sc[key] = d;
            mx = fmaxf(mx, d);
        }
        float ssum = 0.f;
#pragma unroll
        for (int key = 0; key < 32; key++) {
            float e = __expf(sc[key] - mx);
            sc[key] = e; ssum += e;
        }
        float sinv = __fdividef(1.f, ssum);
        float av[8];
#pragma unroll
        for (int i = 0; i < 8; i++) av[i] = 0.f;
#pragma unroll
        for (int key = 0; key < 32; key++) {
            float pw = sc[key];
#pragma unroll
            for (int i = 0; i < 8; i++)
                av[i] += pw * vb[key * 32 + ((hh * 8 + i) ^ key)];
        }
#pragma unroll
        for (int i = 0; i < 8; i++) {
            ull ad = dup2(av[i] * sinv);
            const ulonglong2* wt = (const ulonglong2*)(s->woT + (hh * 8 + i) * 32);
#pragma unroll
            for (int q = 0; q < 8; q++) {
                ulonglong2 w = wt[q];
                o2[2 * q]     = ffma2(w.x, ad, o2[2 * q]);
                o2[2 * q + 1] = ffma2(w.y, ad, o2[2 * q + 1]);
            }
        }
    }

    // ctx layernorm over concat(ln2, o2)
    float m2 = 0.f;
#pragma unroll
    for (int j = 0; j < 16; j++) m2 += hsum2(ln2[j]) + hsum2(o2[j]);
    m2 *= (1.f / 64.f);
    float cv[64];
    float v2 = 0.f;
#pragma unroll
    for (int j = 0; j < 16; j++) {
        float a, b; unpk(ln2[j], a, b);
        a -= m2; b -= m2; v2 += a * a + b * b;
        cv[2 * j] = a; cv[2 * j + 1] = b;
    }
#pragma unroll
    for (int j = 0; j < 16; j++) {
        float a, b; unpk(o2[j], a, b);
        a -= m2; b -= m2; v2 += a * a + b * b;
        cv[32 + 2 * j] = a; cv[33 + 2 * j] = b;
    }
    v2 *= (1.f / 64.f);
    float inv2 = rsqrtf(v2 + 1e-5f);
    ull ctx2[32];
#pragma unroll
    for (int q = 0; q < 32; q++)
        ctx2[q] = pk2(cv[2 * q] * inv2 * s->lncg[2 * q] + s->lncb[2 * q],
                      cv[2 * q + 1] * inv2 * s->lncg[2 * q + 1] + s->lncb[2 * q + 1]);

    ull x12[32];
#pragma unroll
    for (int q = 0; q < 32; q++) {
        float y0 = leaky(dotp<32>(ctx2, s->mlp1 + (2 * q) * 64) + s->m1b[2 * q]);
        float y1 = leaky(dotp<32>(ctx2, s->mlp1 + (2 * q + 1) * 64) + s->m1b[2 * q + 1]);
        x12[q] = pk2(y0, y1);
    }
    ull dh2[16];
#pragma unroll
    for (int q = 0; q < 12; q++) {
        float y0 = leaky(dotp<32>(x12, s->mlp2 + (2 * q) * 64) + s->m2b[2 * q]);
        float y1 = leaky(dotp<32>(x12, s->mlp2 + (2 * q + 1) * 64) + s->m2b[2 * q + 1]);
        dh2[q] = pk2(y0, y1);
    }
#pragma unroll
    for (int q = 0; q < 4; q++)
        dh2[12 + q] = pk2(s->noi[2 * q], s->noi[2 * q + 1]);

    ulonglong2* op = (ulonglong2*)(g_dh + (size_t)ag * 32);
#pragma unroll
    for (int q = 0; q < 8; q++) {
        ulonglong2 v; v.x = dh2[2 * q]; v.y = dh2[2 * q + 1];
        op[q] = v;
    }
}

// ============================ launch ============================
extern "C" void kernel_launch(void* const* d_in, const int* in_sizes, int n_in,
                              void* d_out, int out_size) {
    const float* obs_rel = (const float*)d_in[1];
    const int*   se      = (const int*)d_in[2];
    int n = in_sizes[1] / (OBS * 2);
    int nscene = in_sizes[2] / 2;

    LP pe;
    pe.whh = (const float*)d_in[7];  pe.wih = (const float*)d_in[6];
    pe.emw = (const float*)d_in[4];  pe.emb = (const float*)d_in[5];
    pe.bih = (const float*)d_in[8];  pe.bhh = (const float*)d_in[9];
    pe.obs_rel = obs_rel; pe.se = se;
    pe.dow = nullptr; pe.dob = nullptr; pe.out = nullptr;
    pe.n = n; pe.nscene = nscene;

    LP pd;
    pd.whh = (const float*)d_in[25]; pd.wih = (const float*)d_in[24];
    pd.emw = (const float*)d_in[22]; pd.emb = (const float*)d_in[23];
    pd.bih = (const float*)d_in[26]; pd.bhh = (const float*)d_in[27];
    pd.obs_rel = obs_rel; pd.se = se;
    pd.dow = (const float*)d_in[28]; pd.dob = (const float*)d_in[29];
    pd.out = (float*)d_out;
    pd.n = n; pd.nscene = nscene;

    AP pa;
    pa.se = se; pa.noise_z = (const float*)d_in[3];
    pa.lneg = (const float*)d_in[10]; pa.lneb = (const float*)d_in[11];
    pa.wq = (const float*)d_in[12];   pa.wk = (const float*)d_in[13];
    pa.wv = (const float*)d_in[14];   pa.wo = (const float*)d_in[15];
    pa.lncg = (const float*)d_in[16]; pa.lncb = (const float*)d_in[17];
    pa.m1w = (const float*)d_in[18];  pa.m1b = (const float*)d_in[19];
    pa.m2w = (const float*)d_in[20];  pa.m2b = (const float*)d_in[21];
    pa.n = n; pa.nscene = nscene;

    size_t smL = sizeof(SML);
    size_t smA = sizeof(SMA);
    cudaFuncSetAttribute(enc_kernel,  cudaFuncAttributeMaxDynamicSharedMemorySize, (int)smL);
    cudaFuncSetAttribute(dec_kernel,  cudaFuncAttributeMaxDynamicSharedMemorySize, (int)smL);
    cudaFuncSetAttribute(attn_kernel, cudaFuncAttributeMaxDynamicSharedMemorySize, (int)smA);

    int gridL = (nscene + SCN_BLK - 1) / SCN_BLK;
    int gridA = (nscene + AWARPS - 1) / AWARPS;

    enc_kernel <<<gridL, LTPB, smL>>>(pe);
    attn_kernel<<<gridA, ATPB, smA>>>(pa);
    dec_kernel <<<gridL, LTPB, smL>>>(pd);
}

// round 11
// speedup vs baseline: 1.1880x; 1.0012x over previous
#include <cuda_runtime.h>

// TrajectoryGenerator, round 5: 3-kernel split (enc LSTM / attn+MLP / dec LSTM)
// via __device__ scratch. LSTM kernels: 448 thr (14 warps), 28 scenes/CTA,
// grid=147 (one full wave), 2 agents per lane, rank-2 collapsed input with
// bias/xy folded into packed accumulator inits. fma.rn.f32x2 + tanh.approx.

#define OBS   20
#define PRED  30
#define MAXN  131072

typedef unsigned long long ull;

__device__ static float g_henc[MAXN * 32];   // raw encoder h
__device__ static float g_dh[MAXN * 32];     // decoder initial h

__device__ __forceinline__ ull ffma2(ull a, ull b, ull c) {
    ull d; asm("fma.rn.f32x2 %0, %1, %2, %3;" : "=l"(d) : "l"(a), "l"(b), "l"(c)); return d;
}
__device__ __forceinline__ ull fmul2(ull a, ull b) {
    ull d; asm("mul.rn.f32x2 %0, %1, %2;" : "=l"(d) : "l"(a), "l"(b)); return d;
}
__device__ __forceinline__ ull fadd2_(ull a, ull b) {
    ull d; asm("add.rn.f32x2 %0, %1, %2;" : "=l"(d) : "l"(a), "l"(b)); return d;
}
__device__ __forceinline__ ull dup2(float x) {
    ull d; asm("mov.b64 %0, {%1, %1};" : "=l"(d) : "f"(x)); return d;
}
__device__ __forceinline__ ull pk2(float lo, float hi) {
    ull d; asm("mov.b64 %0, {%1, %2};" : "=l"(d) : "f"(lo), "f"(hi)); return d;
}
__device__ __forceinline__ void unpk(ull a, float& x, float& y) {
    asm("mov.b64 {%0, %1}, %2;" : "=f"(x), "=f"(y) : "l"(a));
}
__device__ __forceinline__ float hsum2(ull a) {
    float x, y; unpk(a, x, y); return x + y;
}
__device__ __forceinline__ float tanh_hw(float x) {
    float y; asm("tanh.approx.f32 %0, %1;" : "=f"(y) : "f"(x)); return y;
}
__device__ __forceinline__ float leaky(float x) { return x > 0.f ? x : 0.01f * x; }

template <int NP>
__device__ __forceinline__ float dotp(const ull* a, const float* wrow) {
    const ulonglong2* w = (const ulonglong2*)wrow;
    ull a0 = 0ull, a1 = 0ull;
#pragma unroll
    for (int q = 0; q < NP / 2; q++) {
        ulonglong2 ww = w[q];
        a0 = ffma2(ww.x, a[2 * q], a0);
        a1 = ffma2(ww.y, a[2 * q + 1], a1);
    }
    return hsum2(fadd2_(a0, a1));
}

// ============================ LSTM kernels ============================
// Per-warp stash: cA(1024f) | cB(1024f) | hpA(1024f as 512 ull)
#define LWARPS 14
#define LTPB   448
#define SCN_BLK 28

struct LP {
    const float* whh;      // [128,32]
    const float* wih;      // [128,16]
    const float* emw;      // [16,2]
    const float* emb;      // [16]
    const float* bih; const float* bhh;
    const float* obs_rel;  // enc: input; dec: last-frame source
    const int*   se;
    const float* dow; const float* dob;   // dec only
    float* out;                            // dec only
    int n; int nscene;
};

struct SML {
    float      whh[4096];
    ulonglong2 gw[128];     // .x = (wx,wy) packed, .y = (bias, 0)
    float      dow[64];
    float      dob[2];
    float      stash[LWARPS * 3072];
};

// One step for two agents. Old h in hA/hB regs; new A h staged via smem hpA,
// new B h staged in registers. c states in smem.
__device__ __forceinline__ void lstm_step2(const float* whh, const ulonglong2* gw,
                                           ull xyA, ull xyB,
                                           ull* hA, ull* hB,
                                           float* cA, float* cB, ull* hpA) {
    ull hBn[16];
#pragma unroll 1
    for (int j = 0; j < 16; j++) {
        float hnA[2], hnB[2];
#pragma unroll
        for (int half = 0; half < 2; half++) {
            const int k = 2 * j + half;
            float gA[4], gB[4];
#pragma unroll
            for (int g = 0; g < 4; g++) {
                const int row = g * 32 + k;
                const ulonglong2* w = (const ulonglong2*)(whh + row * 32);
                ulonglong2 gv = gw[row];
                ull a0 = gv.y, b0 = gv.y;           // (bias, 0)
                ull a1 = fmul2(gv.x, xyA);
                ull b1 = fmul2(gv.x, xyB);
#pragma unroll
                for (int q = 0; q < 8; q++) {
                    ulonglong2 ww = w[q];
                    a0 = ffma2(ww.x, hA[2 * q], a0);
                    a1 = ffma2(ww.y, hA[2 * q + 1], a1);
                    b0 = ffma2(ww.x, hB[2 * q], b0);
                    b1 = ffma2(ww.y, hB[2 * q + 1], b1);
                }
                gA[g] = hsum2(fadd2_(a0, a1));
                gB[g] = hsum2(fadd2_(b0, b1));
            }
            {
                float tf = tanh_hw(0.5f * gA[1]);
                float ti = tanh_hw(0.5f * gA[0]);
                float tg = tanh_hw(gA[2]);
                float to = tanh_hw(0.5f * gA[3]);
                float c = cA[k * 32];
                float hc = 0.5f * c, hg = 0.5f * tg;
                c = fmaf(tf, hc, hc) + fmaf(ti, hg, hg);
                cA[k * 32] = c;
                float tc = tanh_hw(c);
                float htc = 0.5f * tc;
                hnA[half] = fmaf(to, htc, htc);
            }
            {
                float tf = tanh_hw(0.5f * gB[1]);
                float ti = tanh_hw(0.5f * gB[0]);
                float tg = tanh_hw(gB[2]);
                float to = tanh_hw(0.5f * gB[3]);
                float c = cB[k * 32];
                float hc = 0.5f * c, hg = 0.5f * tg;
                c = fmaf(tf, hc, hc) + fmaf(ti, hg, hg);
                cB[k * 32] = c;
                float tc = tanh_hw(c);
                float htc = 0.5f * tc;
                hnB[half] = fmaf(to, htc, htc);
            }
        }
        hpA[j * 32] = pk2(hnA[0], hnA[1]);
        hBn[j] = pk2(hnB[0], hnB[1]);
    }
#pragma unroll
    for (int j = 0; j < 16; j++) { hA[j] = hpA[j * 32]; hB[j] = hBn[j]; }
}

// staging of collapsed input weights: one row per thread (tid<128)
__device__ __forceinline__ void stage_lstm_smem(SML* s, const LP& p, int tid, int tpb, bool dec) {
    for (int i = tid; i < 4096; i += tpb) s->whh[i] = p.whh[i];
    if (tid < 128) {
        int row = tid;
        float wx = 0.f, wy = 0.f, cb = 0.f;
#pragma unroll
        for (int j = 0; j < 16; j++) {
            float w = p.wih[row * 16 + j];
            wx += w * p.emw[j * 2 + 0];
            wy += w * p.emw[j * 2 + 1];
            cb += w * p.emb[j];
        }
        cb += p.bih[row] + p.bhh[row];
        ulonglong2 v;
        v.x = pk2(wx, wy);
        v.y = pk2(cb, 0.f);
        s->gw[row] = v;
    }
    if (dec) {
        for (int i = tid; i < 64; i += tpb) s->dow[i] = p.dow[i];
        if (tid < 2) s->dob[tid] = p.dob[tid];
    }
}

__global__ void __launch_bounds__(LTPB, 1)
enc_kernel(LP p) {
    extern __shared__ float smraw[];
    SML* s = (SML*)smraw;
    const int tid = threadIdx.x, warp = tid >> 5, lane = tid & 31;
    stage_lstm_smem(s, p, tid, LTPB, false);
    __syncthreads();

    const int sceneA = blockIdx.x * SCN_BLK + warp * 2;
    if (sceneA >= p.nscene) return;
    const bool hasB = (sceneA + 1 < p.nscene);
    const int agA = p.se[2 * sceneA] + lane;
    const int agB = (hasB ? p.se[2 * (sceneA + 1)] : p.se[2 * sceneA]) + lane;

    float* wst = s->stash + warp * 3072;
    float* cA = wst + lane;
    float* cB = wst + 1024 + lane;
    ull*  hpA = (ull*)(wst + 2048) + lane;

#pragma unroll
    for (int k = 0; k < 32; k++) { cA[k * 32] = 0.f; cB[k * 32] = 0.f; }
    ull hA[16], hB[16];
#pragma unroll
    for (int j = 0; j < 16; j++) { hA[j] = 0ull; hB[j] = 0ull; }

#pragma unroll 1
    for (int t = 0; t < OBS; t++) {
        float2 a = *(const float2*)(p.obs_rel + ((size_t)t * p.n + agA) * 2);
        float2 b = *(const float2*)(p.obs_rel + ((size_t)t * p.n + agB) * 2);
        lstm_step2(s->whh, s->gw, pk2(a.x, a.y), pk2(b.x, b.y), hA, hB, cA, cB, hpA);
    }

    ulonglong2* oA = (ulonglong2*)(g_henc + (size_t)agA * 32);
    ulonglong2* oB = (ulonglong2*)(g_henc + (size_t)agB * 32);
#pragma unroll
    for (int q = 0; q < 8; q++) {
        ulonglong2 va; va.x = hA[2 * q]; va.y = hA[2 * q + 1];
        oA[q] = va;
        if (hasB) { ulonglong2 vb; vb.x = hB[2 * q]; vb.y = hB[2 * q + 1]; oB[q] = vb; }
    }
}

__global__ void __launch_bounds__(LTPB, 1)
dec_kernel(LP p) {
    extern __shared__ float smraw[];
    SML* s = (SML*)smraw;
    const int tid = threadIdx.x, warp = tid >> 5, lane = tid & 31;
    stage_lstm_smem(s, p, tid, LTPB, true);
    __syncthreads();

    const int sceneA = blockIdx.x * SCN_BLK + warp * 2;
    if (sceneA >= p.nscene) return;
    const bool hasB = (sceneA + 1 < p.nscene);
    const int agA = p.se[2 * sceneA] + lane;
    const int agB = (hasB ? p.se[2 * (sceneA + 1)] : p.se[2 * sceneA]) + lane;

    float* wst = s->stash + warp * 3072;
    float* cA = wst + lane;
    float* cB = wst + 1024 + lane;
    ull*  hpA = (ull*)(wst + 2048) + lane;

#pragma unroll
    for (int k = 0; k < 32; k++) { cA[k * 32] = 0.f; cB[k * 32] = 0.f; }

    ull hA[16], hB[16];
    {
        const ulonglong2* iA = (const ulonglong2*)(g_dh + (size_t)agA * 32);
        const ulonglong2* iB = (const ulonglong2*)(g_dh + (size_t)agB * 32);
#pragma unroll
        for (int q = 0; q < 8; q++) {
            ulonglong2 va = iA[q]; hA[2 * q] = va.x; hA[2 * q + 1] = va.y;
            ulonglong2 vb = iB[q]; hB[2 * q] = vb.x; hB[2 * q + 1] = vb.y;
        }
    }

    float2 a0v = *(const float2*)(p.obs_rel + ((size_t)(OBS - 1) * p.n + agA) * 2);
    float2 b0v = *(const float2*)(p.obs_rel + ((size_t)(OBS - 1) * p.n + agB) * 2);
    ull xyA = pk2(a0v.x, a0v.y), xyB = pk2(b0v.x, b0v.y);

#pragma unroll 1
    for (int t = 0; t < PRED; t++) {
        lstm_step2(s->whh, s->gw, xyA, xyB, hA, hB, cA, cB, hpA);
        float a0 = dotp<16>(hA, s->dow) + s->dob[0];
        float a1 = dotp<16>(hA, s->dow + 32) + s->dob[1];
        float b0 = dotp<16>(hB, s->dow) + s->dob[0];
        float b1 = dotp<16>(hB, s->dow + 32) + s->dob[1];
        *(float2*)(p.out + ((size_t)t * p.n + agA) * 2) = make_float2(a0, a1);
        if (hasB)
            *(float2*)(p.out + ((size_t)t * p.n + agB) * 2) = make_float2(b0, b1);
        xyA = pk2(a0, a1); xyB = pk2(b0, b1);
    }
}

// ============================ attention kernel ============================
#define AWARPS 8
#define ATPB   256

struct AP {
    const int*   se;
    const float* noise_z;
    const float* lneg; const float* lneb;
    const float* wq; const float* wk; const float* wv; const float* wo;
    const float* lncg; const float* lncb;
    const float* m1w; const float* m1b;
    const float* m2w; const float* m2b;
    int n; int nscene;
};

struct SMA {
    float wq[1024], wk[1024], wv[1024], woT[1024];
    float mlp1[4096];
    float mlp2[1536];
    float lneg[32], lneb[32], lncg[64], lncb[64];
    float m1b[64], m2b[24], noi[8];
    float kv[AWARPS * 2048];
};

__global__ void __launch_bounds__(ATPB)
attn_kernel(AP p) {
    extern __shared__ float smraw[];
    SMA* s = (SMA*)smraw;
    const int tid = threadIdx.x, warp = tid >> 5, lane = tid & 31;

    for (int i = tid; i < 1024; i += ATPB) { s->wq[i] = p.wq[i]; s->wk[i] = p.wk[i]; s->wv[i] = p.wv[i]; }
    for (int i = tid; i < 1024; i += ATPB) { int r = i >> 5, c = i & 31; s->woT[i] = p.wo[c * 32 + r]; }
    for (int i = tid; i < 4096; i += ATPB) s->mlp1[i] = p.m1w[i];
    for (int i = tid; i < 1536; i += ATPB) s->mlp2[i] = p.m2w[i];
    for (int i = tid; i < 32; i += ATPB) { s->lneg[i] = p.lneg[i]; s->lneb[i] = p.lneb[i]; }
    for (int i = tid; i < 64; i += ATPB) { s->lncg[i] = p.lncg[i]; s->lncb[i] = p.lncb[i]; s->m1b[i] = p.m1b[i]; }
    for (int i = tid; i < 24; i += ATPB) s->m2b[i] = p.m2b[i];
    for (int i = tid; i < 8; i += ATPB) s->noi[i] = p.noise_z[i];
    __syncthreads();

    const int scene = blockIdx.x * AWARPS + warp;
    if (scene >= p.nscene) return;
    const int ag = p.se[2 * scene] + lane;

    // load h_enc and layernorm
    ull h[16];
    {
        const ulonglong2* ip = (const ulonglong2*)(g_henc + (size_t)ag * 32);
#pragma unroll
        for (int q = 0; q < 8; q++) { ulonglong2 v = ip[q]; h[2 * q] = v.x; h[2 * q + 1] = v.y; }
    }
    float m = 0.f;
#pragma unroll
    for (int j = 0; j < 16; j++) m += hsum2(h[j]);
    m *= (1.f / 32.f);
    float var = 0.f;
    float hl[32];
#pragma unroll
    for (int j = 0; j < 16; j++) {
        float a, b; unpk(h[j], a, b);
        a -= m; b -= m; var += a * a + b * b;
        hl[2 * j] = a; hl[2 * j + 1] = b;
    }
    var *= (1.f / 32.f);
    float inv = rsqrtf(var + 1e-5f);
    ull ln2[16];
#pragma unroll
    for (int j = 0; j < 16; j++)
        ln2[j] = pk2(hl[2 * j] * inv * s->lneg[2 * j] + s->lneb[2 * j],
                     hl[2 * j + 1] * inv * s->lneg[2 * j + 1] + s->lneb[2 * j + 1]);

    float* kb = s->kv + warp * 2048;
    float* vb = kb + 1024;
#pragma unroll
    for (int i = 0; i < 32; i++)
        kb[lane * 32 + (i ^ lane)] = dotp<16>(ln2, s->wk + i * 32);
#pragma unroll
    for (int i = 0; i < 32; i++)
        vb[lane * 32 + (i ^ lane)] = dotp<16>(ln2, s->wv + i * 32);
    __syncwarp();

    ull o2[16];
#pragma unroll
    for (int q = 0; q < 16; q++) o2[q] = 0ull;

#pragma unroll 1
    for (int hh = 0; hh < 4; hh++) {
        float qh[8];
#pragma unroll
        for (int i = 0; i < 8; i++) qh[i] = dotp<16>(ln2, s->wq + (hh * 8 + i) * 32);
        float sc[32];
        float mx = -3.4e38f;
#pragma unroll
        for (int key = 0; key < 32; key++) {
            float d = 0.f;
#pragma unroll
            for (int i = 0; i < 8; i++)
                d += qh[i] * kb[key * 32 + ((hh * 8 + i) ^ key)];
            d *= 0.3535533905932738f;
            sc[key] = d;
            mx = fmaxf(mx, d);
        }
        float ssum = 0.f;
#pragma unroll
        for (int key = 0; key < 32; key++) {
            float e = __expf(sc[key] - mx);
            sc[key] = e; ssum += e;
        }
        float sinv = __fdividef(1.f, ssum);
        float av[8];
#pragma unroll
        for (int i = 0; i < 8; i++) av[i] = 0.f;
#pragma unroll
        for (int key = 0; key < 32; key++) {
            float pw = sc[key];
#pragma unroll
            for (int i = 0; i < 8; i++)
                av[i] += pw * vb[key * 32 + ((hh * 8 + i) ^ key)];
        }
#pragma unroll
        for (int i = 0; i < 8; i++) {
            ull ad = dup2(av[i] * sinv);
            const ulonglong2* wt = (const ulonglong2*)(s->woT + (hh * 8 + i) * 32);
#pragma unroll
            for (int q = 0; q < 8; q++) {
                ulonglong2 w = wt[q];
                o2[2 * q]     = ffma2(w.x, ad, o2[2 * q]);
                o2[2 * q + 1] = ffma2(w.y, ad, o2[2 * q + 1]);
            }
        }
    }

    // ctx layernorm over concat(ln2, o2)
    float m2 = 0.f;
#pragma unroll
    for (int j = 0; j < 16; j++) m2 += hsum2(ln2[j]) + hsum2(o2[j]);
    m2 *= (1.f / 64.f);
    float cv[64];
    float v2 = 0.f;
#pragma unroll
    for (int j = 0; j < 16; j++) {
        float a, b; unpk(ln2[j], a, b);
        a -= m2; b -= m2; v2 += a * a + b * b;
        cv[2 * j] = a; cv[2 * j + 1] = b;
    }
#pragma unroll
    for (int j = 0; j < 16; j++) {
        float a, b; unpk(o2[j], a, b);
        a -= m2; b -= m2; v2 += a * a + b * b;
        cv[32 + 2 * j] = a; cv[33 + 2 * j] = b;
    }
    v2 *= (1.f / 64.f);
    float inv2 = rsqrtf(v2 + 1e-5f);
    ull ctx2[32];
#pragma unroll
    for (int q = 0; q < 32; q++)
        ctx2[q] = pk2(cv[2 * q] * inv2 * s->lncg[2 * q] + s->lncb[2 * q],
                      cv[2 * q + 1] * inv2 * s->lncg[2 * q + 1] + s->lncb[2 * q + 1]);

    ull x12[32];
#pragma unroll
    for (int q = 0; q < 32; q++) {
        float y0 = leaky(dotp<32>(ctx2, s->mlp1 + (2 * q) * 64) + s->m1b[2 * q]);
        float y1 = leaky(dotp<32>(ctx2, s->mlp1 + (2 * q + 1) * 64) + s->m1b[2 * q + 1]);
        x12[q] = pk2(y0, y1);
    }
    ull dh2[16];
#pragma unroll
    for (int q = 0; q < 12; q++) {
        float y0 = leaky(dotp<32>(x12, s->mlp2 + (2 * q) * 64) + s->m2b[2 * q]);
        float y1 = leaky(dotp<32>(x12, s->mlp2 + (2 * q + 1) * 64) + s->m2b[2 * q + 1]);
        dh2[q] = pk2(y0, y1);
    }
#pragma unroll
    for (int q = 0; q < 4; q++)
        dh2[12 + q] = pk2(s->noi[2 * q], s->noi[2 * q + 1]);

    ulonglong2* op = (ulonglong2*)(g_dh + (size_t)ag * 32);
#pragma unroll
    for (int q = 0; q < 8; q++) {
        ulonglong2 v; v.x = dh2[2 * q]; v.y = dh2[2 * q + 1];
        op[q] = v;
    }
}

// ============================ launch ============================
extern "C" void kernel_launch(void* const* d_in, const int* in_sizes, int n_in,
                              void* d_out, int out_size) {
    const float* obs_rel = (const float*)d_in[1];
    const int*   se      = (const int*)d_in[2];
    int n = in_sizes[1] / (OBS * 2);
    int nscene = in_sizes[2] / 2;

    LP pe;
    pe.whh = (const float*)d_in[7];  pe.wih = (const float*)d_in[6];
    pe.emw = (const float*)d_in[4];  pe.emb = (const float*)d_in[5];
    pe.bih = (const float*)d_in[8];  pe.bhh = (const float*)d_in[9];
    pe.obs_rel = obs_rel; pe.se = se;
    pe.dow = nullptr; pe.dob = nullptr; pe.out = nullptr;
    pe.n = n; pe.nscene = nscene;

    LP pd;
    pd.whh = (const float*)d_in[25]; pd.wih = (const float*)d_in[24];
    pd.emw = (const float*)d_in[22]; pd.emb = (const float*)d_in[23];
    pd.bih = (const float*)d_in[26]; pd.bhh = (const float*)d_in[27];
    pd.obs_rel = obs_rel; pd.se = se;
    pd.dow = (const float*)d_in[28]; pd.dob = (const float*)d_in[29];
    pd.out = (float*)d_out;
    pd.n = n; pd.nscene = nscene;

    AP pa;
    pa.se = se; pa.noise_z = (const float*)d_in[3];
    pa.lneg = (const float*)d_in[10]; pa.lneb = (const float*)d_in[11];
    pa.wq = (const float*)d_in[12];   pa.wk = (const float*)d_in[13];
    pa.wv = (const float*)d_in[14];   pa.wo = (const float*)d_in[15];
    pa.lncg = (const float*)d_in[16]; pa.lncb = (const float*)d_in[17];
    pa.m1w = (const float*)d_in[18];  pa.m1b = (const float*)d_in[19];
    pa.m2w = (const float*)d_in[20];  pa.m2b = (const float*)d_in[21];
    pa.n = n; pa.nscene = nscene;

    size_t smL = sizeof(SML);
    size_t smA = sizeof(SMA);
    cudaFuncSetAttribute(enc_kernel,  cudaFuncAttributeMaxDynamicSharedMemorySize, (int)smL);
    cudaFuncSetAttribute(dec_kernel,  cudaFuncAttributeMaxDynamicSharedMemorySize, (int)smL);
    cudaFuncSetAttribute(attn_kernel, cudaFuncAttributeMaxDynamicSharedMemorySize, (int)smA);

    int gridL = (nscene + SCN_BLK - 1) / SCN_BLK;
    int gridA = (nscene + AWARPS - 1) / AWARPS;

    enc_kernel <<<gridL, LTPB, smL>>>(pe);
    attn_kernel<<<gridA, ATPB, smA>>>(pa);
    dec_kernel <<<gridL, LTPB, smL>>>(pd);
}